// round 9
// baseline (speedup 1.0000x reference)
#include <cuda_runtime.h>

// MemoryOnlyTitan — algebraic collapse of the reference:
// state0 == 0 -> write softmax uniform -> every memory slot = mean_t v
//             -> read softmax uniform  -> mem_out[b,t,:] = vbar[b,:] for all t
// vbar  = (sum_t c / T) @ Wv + bv          (c = [pm; x])
// row   = (LN(vbar)*gamma + beta) @ Wout + bout
// out[b,t,:] = row[b,:]  broadcast over all T = P+S tokens.
//
// 3 kernels: k_sum (64MB read -> csum atomics), k_mid (gemv+LN+gemv, 4 blocks),
// k_bcast (67MB write + csum reset for the next graph replay).

#define Bn   4
#define Sn   8192
#define Dn   512
#define Pn   32
#define Tn   (Pn + Sn)          // 8224
#define EPSf 1e-5f

#define XB      256             // x-sum blocks per batch
#define RP      (Sn / XB)       // 32 rows per block
#define D4      (Dn / 4)        // 128 float4 per row
#define N4      (Tn * D4)       // 1052672 float4 per batch

// scratch (allocation forbidden -> device globals; csum reset by k_bcast tail)
__device__ float g_csum[Bn * Dn];      // starts zero (static init / prev-run reset)
__device__ float g_outrow[Bn * Dn];

// ---------------------------------------------------------------------------
// Kernel 1: per-batch column sums of c = [pm; x] into g_csum via atomics.
// grid = (XB+1, Bn), block = 128. blockIdx.x < XB -> x slice; == XB -> pm.
__global__ void k_sum(const float* __restrict__ x, const float* __restrict__ pm) {
    const int b  = blockIdx.y;
    const int t4 = threadIdx.x;                 // 0..127 (float4 column group)

    float4 acc = make_float4(0.f, 0.f, 0.f, 0.f);
    if (blockIdx.x < XB) {
        const float4* __restrict__ src = reinterpret_cast<const float4*>(x)
            + (size_t)b * Sn * D4 + (size_t)blockIdx.x * RP * D4 + t4;
#pragma unroll 8
        for (int i = 0; i < RP; ++i) {
            float4 v = src[(size_t)i * D4];
            acc.x += v.x; acc.y += v.y; acc.z += v.z; acc.w += v.w;
        }
    } else {
        const float4* __restrict__ src = reinterpret_cast<const float4*>(pm) + t4;
#pragma unroll
        for (int i = 0; i < Pn; ++i) {
            float4 v = src[(size_t)i * D4];
            acc.x += v.x; acc.y += v.y; acc.z += v.z; acc.w += v.w;
        }
    }
    float* dst = &g_csum[b * Dn + t4 * 4];
    atomicAdd(dst + 0, acc.x);
    atomicAdd(dst + 1, acc.y);
    atomicAdd(dst + 2, acc.z);
    atomicAdd(dst + 3, acc.w);
}

// ---------------------------------------------------------------------------
// Kernel 2: fused middle stage, one block per batch, 512 threads.
//   vbar = csum/T @ Wv + bv ; normed = LN(vbar)*gamma + beta ;
//   outrow = normed @ Wout + bout
// Thread layout: p = tid/128 (K-split part), j = tid%128 (float4 d-group).
__global__ __launch_bounds__(512, 1)
void k_mid(const float* __restrict__ Wv,  const float* __restrict__ bv,
           const float* __restrict__ gamma, const float* __restrict__ beta,
           const float* __restrict__ Wout, const float* __restrict__ bout) {
    __shared__ float  act[Dn];          // activation vector (csum/T, then normed)
    __shared__ float4 part[4][D4];      // K-split partials
    __shared__ float  red[16];
    __shared__ float  bc[2];

    const int b   = blockIdx.x;
    const int tid = threadIdx.x;
    const int p   = tid >> 7;           // 0..3
    const int j   = tid & 127;          // 0..127
    const int e0  = p * 128;

    act[tid] = g_csum[b * Dn + tid] * (1.f / (float)Tn);
    __syncthreads();

    // ---- GEMV 1: vbar4[j] = sum_e act[e] * Wv[e][4j..4j+3] ----
    const float4* __restrict__ Wv4 = reinterpret_cast<const float4*>(Wv);
    float4 a = make_float4(0.f, 0.f, 0.f, 0.f);
#pragma unroll 8
    for (int e = 0; e < 128; ++e) {
        const float  c = act[e0 + e];
        const float4 w = Wv4[(size_t)(e0 + e) * D4 + j];
        a.x += c * w.x; a.y += c * w.y; a.z += c * w.z; a.w += c * w.w;
    }
    part[p][j] = a;
    __syncthreads();

    float4 vb = make_float4(0.f, 0.f, 0.f, 0.f);
    if (p == 0) {
        const float4 bv4 = reinterpret_cast<const float4*>(bv)[j];
        float4 q0 = part[0][j], q1 = part[1][j], q2 = part[2][j], q3 = part[3][j];
        vb.x = q0.x + q1.x + q2.x + q3.x + bv4.x;
        vb.y = q0.y + q1.y + q2.y + q3.y + bv4.y;
        vb.z = q0.z + q1.z + q2.z + q3.z + bv4.z;
        vb.w = q0.w + q1.w + q2.w + q3.w + bv4.w;
    }

    // ---- LayerNorm (values live in threads p==0 as float4) ----
    float s = (p == 0) ? (vb.x + vb.y + vb.z + vb.w) : 0.f;
#pragma unroll
    for (int o = 16; o; o >>= 1) s += __shfl_xor_sync(0xffffffffu, s, o);
    if ((tid & 31) == 0) red[tid >> 5] = s;
    __syncthreads();
    if (tid == 0) {
        float t = 0.f;
#pragma unroll
        for (int i = 0; i < 16; ++i) t += red[i];
        bc[0] = t * (1.f / (float)Dn);
    }
    __syncthreads();
    const float mu = bc[0];

    float4 df = make_float4(vb.x - mu, vb.y - mu, vb.z - mu, vb.w - mu);
    float q = (p == 0) ? (df.x * df.x + df.y * df.y + df.z * df.z + df.w * df.w) : 0.f;
#pragma unroll
    for (int o = 16; o; o >>= 1) q += __shfl_xor_sync(0xffffffffu, q, o);
    if ((tid & 31) == 0) red[tid >> 5] = q;
    __syncthreads();
    if (tid == 0) {
        float t = 0.f;
#pragma unroll
        for (int i = 0; i < 16; ++i) t += red[i];
        bc[1] = rsqrtf(t * (1.f / (float)Dn) + EPSf);
    }
    __syncthreads();
    const float rstd = bc[1];

    if (p == 0) {
        const float4 g4 = reinterpret_cast<const float4*>(gamma)[j];
        const float4 b4 = reinterpret_cast<const float4*>(beta)[j];
        act[j * 4 + 0] = df.x * rstd * g4.x + b4.x;
        act[j * 4 + 1] = df.y * rstd * g4.y + b4.y;
        act[j * 4 + 2] = df.z * rstd * g4.z + b4.z;
        act[j * 4 + 3] = df.w * rstd * g4.w + b4.w;
    }
    __syncthreads();

    // ---- GEMV 2: outrow4[j] = sum_e act[e] * Wout[e][4j..4j+3] + bout ----
    const float4* __restrict__ Wo4 = reinterpret_cast<const float4*>(Wout);
    float4 a2 = make_float4(0.f, 0.f, 0.f, 0.f);
#pragma unroll 8
    for (int e = 0; e < 128; ++e) {
        const float  c = act[e0 + e];
        const float4 w = Wo4[(size_t)(e0 + e) * D4 + j];
        a2.x += c * w.x; a2.y += c * w.y; a2.z += c * w.z; a2.w += c * w.w;
    }
    part[p][j] = a2;
    __syncthreads();

    if (p == 0) {
        const float4 bo4 = reinterpret_cast<const float4*>(bout)[j];
        float4 q0 = part[0][j], q1 = part[1][j], q2 = part[2][j], q3 = part[3][j];
        float4 o;
        o.x = q0.x + q1.x + q2.x + q3.x + bo4.x;
        o.y = q0.y + q1.y + q2.y + q3.y + bo4.y;
        o.z = q0.z + q1.z + q2.z + q3.z + bo4.z;
        o.w = q0.w + q1.w + q2.w + q3.w + bo4.w;
        reinterpret_cast<float4*>(g_outrow)[b * D4 + j] = o;
    }
}

// ---------------------------------------------------------------------------
// Kernel 3: broadcast outrow[b,:] to all Tn tokens (67 MB coalesced stores),
// and reset g_csum for the next graph replay (csum was fully consumed by
// k_mid, which precedes this kernel in stream order).
__global__ void k_bcast(float4* __restrict__ out) {
    __shared__ float4 row[D4];
    const int b = blockIdx.y;
    if (threadIdx.x < D4)
        row[threadIdx.x] = reinterpret_cast<const float4*>(g_outrow)[b * D4 + threadIdx.x];
    __syncthreads();

    const unsigned base = blockIdx.x * 2048u + threadIdx.x;
    const float4 val = row[threadIdx.x & (D4 - 1)];   // 256 % 128 == 0 keeps col fixed
    float4* __restrict__ ob = out + (size_t)b * N4;
#pragma unroll
    for (int j = 0; j < 8; ++j) ob[base + j * 256u] = val;

    if (blockIdx.x == 0) {                            // accumulator reset for next run
        g_csum[b * Dn + threadIdx.x]       = 0.f;
        g_csum[b * Dn + threadIdx.x + 256] = 0.f;
    }
}

// ---------------------------------------------------------------------------
extern "C" void kernel_launch(void* const* d_in, const int* in_sizes, int n_in,
                              void* d_out, int out_size) {
    const float* x     = (const float*)d_in[0];
    const float* pm    = (const float*)d_in[1];
    // d_in[2] Wk, d_in[3] bk, d_in[6] Wq, d_in[7] bq -- unused (zero-state algebra)
    const float* Wv    = (const float*)d_in[4];
    const float* bv    = (const float*)d_in[5];
    const float* gamma = (const float*)d_in[8];
    const float* beta  = (const float*)d_in[9];
    const float* Wout  = (const float*)d_in[10];
    const float* bout  = (const float*)d_in[11];

    k_sum  <<<dim3(XB + 1, Bn), 128>>>(x, pm);
    k_mid  <<<Bn, 512>>>(Wv, bv, gamma, beta, Wout, bout);
    k_bcast<<<dim3(N4 / (256 * 8), Bn), 256>>>((float4*)d_out);
}